// round 16
// baseline (speedup 1.0000x reference)
#include <cuda_runtime.h>
#include <math.h>

#define BB   8
#define HH   256
#define WW   256
#define HW   (HH*WW)
#define RPB  4
#define NBLK (BB*HH/RPB)   // 512 blocks, 64 per image

// Scratch (no device allocations allowed): per-block partials + ticket.
__device__ float    g_pp[NBLK];
__device__ float    g_pw[NBLK];
__device__ float    g_pc[NBLK];
__device__ unsigned g_ticket;     // zero-init; last block resets to 0

__device__ __forceinline__ float fsqrt_approx(float x) {
    float r;
    asm("sqrt.approx.f32 %0, %1;" : "=f"(r) : "f"(x));
    return r;                      // sqrt.approx(0)=0; rel err ~1e-7 << 1e-3 budget
}

// ---------------------------------------------------------------------------
// Fused kernel: one block per 4 rows (same image), one thread per column.
//  - Prologue issues ALL gmem loads together (8 logits + 12 target rows).
//  - Vertical nearest-1/0 via a 12-bit column word: per row, below-dir uses
//    clz (clz(0) auto-rejects via the r<=4 trust gate), up-dir uses guarded
//    ffs. Results trusted only for r<=4 (symmetric window coverage); r>4
//    falls into the exact serial gmem tail -- identical to proven behavior.
//  - Horizontal envelope: r<=2 unconditional, r=3..4 gated (>4), serial exact
//    tail gated (>25). Bit-exact vs reference (order-independent min).
//  - sqrt.approx for the two sqrts (1 MUFU each vs IEEE sequence).
//  - Ballot counts; 2-var shuffle tree; last-block global reduction
//    (threadfence + ticket; deterministic order).
// ---------------------------------------------------------------------------
__global__ void __launch_bounds__(256) fused_kernel(
    const float* __restrict__ logits, const int* __restrict__ targets,
    float* __restrict__ out) {
    int blk = blockIdx.x;          // 0..511
    int b   = blk >> 6;            // image
    int h0  = (blk & 63) * RPB;    // first of 4 rows
    int w   = threadIdx.x;

    const int* tcol = targets + b * HW + w;   // column w, stride WW

    // ---- prologue: issue ALL gmem loads together (20 outstanding LDGs) ----
    const float* Lp0 = logits + (b * 2 + 0) * HW + h0 * WW + w;
    const float* Lp1 = logits + (b * 2 + 1) * HW + h0 * WW + w;
    float l0_[RPB], l1_[RPB];
#pragma unroll
    for (int i = 0; i < RPB; i++) { l0_[i] = Lp0[i * WW]; l1_[i] = Lp1[i * WW]; }

    int t[RPB + 8];                // rows h0-4 .. h0+7
    if (h0 >= 4 && h0 + RPB + 3 < HH) {       // interior: no clamping
#pragma unroll
        for (int j = 0; j < RPB + 8; j++) t[j] = tcol[(h0 - 4 + j) * WW];
    } else {
#pragma unroll
        for (int j = 0; j < RPB + 8; j++) {
            int hh = min(max(h0 - 4 + j, 0), HH - 1);
            t[j] = tcol[hh * WW];
        }
    }

    __shared__ float2 srow[RPB][WW + 16];     // +-8 BIG pads
    if (w < 8) {
#pragma unroll
        for (int i = 0; i < RPB; i++) {
            srow[i][w]          = make_float2(1e9f, 1e9f);
            srow[i][WW + 8 + w] = make_float2(1e9f, 1e9f);
        }
    }

    // ---- column word: bit j = t[j] (rows h0-4+j), j=0..11 ----
    unsigned c = 0;
#pragma unroll
    for (int j = 0; j < RPB + 8; j++) c |= ((unsigned)t[j]) << j;
    unsigned cn = (~c) & 0xFFFu;   // zeros-as-ones, masked to the 12 valid rows

    float d2p_[RPB], d2n_[RPB];

#pragma unroll
    for (int i = 0; i < RPB; i++) {
        int hl = i + 4;
        int me = (int)((c >> hl) & 1u);

        // nearest 1: below via clz (b==0 -> dist hl+1 >= 5, auto-rejected);
        //            above via guarded ffs
        unsigned bl1 = c & ((1u << hl) - 1u);
        int dD1 = hl - (31 - __clz(bl1));      // = hl-pos of highest set bit
        unsigned up1 = c >> (hl + 1);
        int dU1 = up1 ? __ffs(up1) : 8;
        int mn1 = min(dD1, dU1);
        int r1  = me ? 0 : ((mn1 <= 4) ? mn1 : 256);

        // nearest 0: same on complement
        unsigned bl0 = cn & ((1u << hl) - 1u);
        int dD0 = hl - (31 - __clz(bl0));
        unsigned up0 = cn >> (hl + 1);
        int dU0 = up0 ? __ffs(up0) : 8;
        int mn0 = min(dD0, dU0);
        int r0  = (me == 0) ? 0 : ((mn0 <= 4) ? mn0 : 256);

        if ((r1 | r0) >= 256) {               // rare exact gmem tail
            int h = h0 + i;
#pragma unroll 1
            for (int r = 5; r < HH; r++) {
                if ((r1 | r0) < 256) break;
                int tu = tcol[max(h - r, 0) * WW];
                int td = tcol[min(h + r, HH - 1) * WW];
                if (r1 == 256 && (tu | td))      r1 = r;
                if (r0 == 256 && (tu & td) == 0) r0 = r;
            }
        }
        d2p_[i] = (r1 <= 255) ? (float)(r1 * r1) : 1e9f;
        d2n_[i] = (r0 <= 255) ? (float)(r0 * r0) : 1e9f;
        srow[i][8 + w] = make_float2(d2p_[i], d2n_[i]);
    }
    __syncthreads();

    // sigmoid while other warps are in the barrier / LDS phase
    float pred_[RPB];
#pragma unroll
    for (int i = 0; i < RPB; i++)
        pred_[i] = __fdividef(1.0f, 1.0f + __expf(l0_[i] - l1_[i]));

    float accP = 0.f, accW = 0.f;

#pragma unroll
    for (int i = 0; i < RPB; i++) {
        const float2* cp = &srow[i][8 + w];
        float bp = d2p_[i], bn = d2n_[i];

        // unconditional prefix r=1..2 (4 independent LDS.64, one wall)
        float2 L1 = cp[-1], R1 = cp[1];
        float2 L2 = cp[-2], R2 = cp[2];
        bp = fminf(bp, fminf(L1.x, R1.x) + 1.0f); bn = fminf(bn, fminf(L1.y, R1.y) + 1.0f);
        bp = fminf(bp, fminf(L2.x, R2.x) + 4.0f); bn = fminf(bn, fminf(L2.y, R2.y) + 4.0f);

        if (fmaxf(bp, bn) > 4.0f) {           // r>=3 can matter only if best>r^2>=9>4
            float2 L3 = cp[-3], R3 = cp[3];
            float2 L4 = cp[-4], R4 = cp[4];
            bp = fminf(bp, fminf(L3.x, R3.x) + 9.0f);  bn = fminf(bn, fminf(L3.y, R3.y) + 9.0f);
            bp = fminf(bp, fminf(L4.x, R4.x) + 16.0f); bn = fminf(bn, fminf(L4.y, R4.y) + 16.0f);

            if (fmaxf(bp, bn) > 25.0f) {      // rare exact serial tail
#pragma unroll 1
                for (int r = 5; r < WW; r++) {
                    float rr = (float)(r * r);
                    if (rr >= bp && rr >= bn) break;
                    if (w - r >= 0) {
                        float2 a = srow[i][8 + w - r];
                        bp = fminf(bp, a.x + rr); bn = fminf(bn, a.y + rr);
                    }
                    if (w + r < WW) {
                        float2 d = srow[i][8 + w + r];
                        bp = fminf(bp, d.x + rr); bn = fminf(bn, d.y + rr);
                    }
                }
            }
        }

        accP += pred_[i];
        accW += pred_[i] * (fsqrt_approx(bp) - fsqrt_approx(bn));
    }

    // ---- warp counts via ballots (warp-uniform) ----
    unsigned m = 0xFFFFFFFFu;
    int wcnt = 0;
#pragma unroll
    for (int i = 0; i < RPB; i++)
        wcnt += __popc(__ballot_sync(m, (c >> (i + 4)) & 1u));
    float cv = (float)wcnt;

    // ---- deterministic block reduction (2 shuffled vars, 1 barrier) ----
#pragma unroll
    for (int o = 16; o > 0; o >>= 1) {
        accP += __shfl_down_sync(m, accP, o);
        accW += __shfl_down_sync(m, accW, o);
    }
    __shared__ float rr0[8], rr1[8], rr2[8];
    if ((w & 31) == 0) {
        rr0[w >> 5] = accP; rr1[w >> 5] = accW; rr2[w >> 5] = cv;
    }
    __syncthreads();

    __shared__ bool s_last;
    if (w == 0) {
        float s0 = 0.f, s1 = 0.f, s2 = 0.f;
#pragma unroll
        for (int i = 0; i < 8; i++) { s0 += rr0[i]; s1 += rr1[i]; s2 += rr2[i]; }
        g_pp[blk] = s0;
        g_pw[blk] = s1;
        g_pc[blk] = s2;
        __threadfence();
        unsigned tk = atomicAdd(&g_ticket, 1u);
        s_last = (tk == (unsigned)(NBLK - 1));
    }
    __syncthreads();
    if (!s_last) return;

    // ---- last block: global reduction (deterministic order) ----
    int wb   = w >> 5;             // batch handled by this warp
    int lane = w & 31;
    int base = wb * 64;            // 64 partials per image
    float s0 = __ldcg(&g_pp[base + lane]) + __ldcg(&g_pp[base + 32 + lane]);
    float s1 = __ldcg(&g_pw[base + lane]) + __ldcg(&g_pw[base + 32 + lane]);
    float s2 = __ldcg(&g_pc[base + lane]) + __ldcg(&g_pc[base + 32 + lane]);
#pragma unroll
    for (int o = 16; o > 0; o >>= 1) {
        s0 += __shfl_down_sync(m, s0, o);
        s1 += __shfl_down_sync(m, s1, o);
        s2 += __shfl_down_sync(m, s2, o);
    }
    __shared__ float pb[8];
    if (lane == 0) {
        float inv = 1.0f / (float)HW;
        float mean_pred = s0 * inv;
        float mean_w    = s1 * inv;
        float per_b;
        if (s2 == 0.0f)           per_b = mean_pred;
        else if (s2 == (float)HW) per_b = 1.0f - mean_pred;
        else                      per_b = mean_w;
        pb[wb] = per_b;
    }
    __syncthreads();
    if (w == 0) {
        float total = 0.f;
#pragma unroll
        for (int i = 0; i < BB; i++) total += pb[i];
        out[0] = total / (float)BB;
        g_ticket = 0;                          // reset for next graph replay
    }
}

extern "C" void kernel_launch(void* const* d_in, const int* in_sizes, int n_in,
                              void* d_out, int out_size) {
    const float* logits  = (const float*)d_in[0];
    const int*   targets = (const int*)d_in[1];
    float*       out     = (float*)d_out;

    fused_kernel<<<NBLK, 256>>>(logits, targets, out);
}

// round 17
// speedup vs baseline: 1.1095x; 1.1095x over previous
#include <cuda_runtime.h>
#include <math.h>

#define BB   8
#define HH   256
#define WW   256
#define HW   (HH*WW)
#define NBLK (BB*HH/4)     // 512 blocks: 4 rows x 256 cols each

// Scratch (no device allocations allowed): per-block partials + ticket.
__device__ float    g_pp[NBLK];
__device__ float    g_pw[NBLK];
__device__ float    g_pc[NBLK];
__device__ unsigned g_ticket;     // zero-init; last block resets to 0

__device__ __forceinline__ float fsqrt_approx(float x) {
    float r;
    asm("sqrt.approx.f32 %0, %1;" : "=f"(r) : "f"(x));
    return r;                      // sqrt.approx(0)=0; rel err ~1e-7 << 1e-3 budget
}

// ---------------------------------------------------------------------------
// Pixel-quad kernel: block = 4 rows x 256 cols; thread = 4 adjacent columns
// of ONE row (q = w&63 -> cols 4q..4q+3, i = w>>6 -> row h0+i).
//  - targets: 9 x LDG.128 (rows h-4..h+4, int4); logits: 2 x LDG.128.
//  - vertical nearest-1/0 per column from 9-bit words (clz/ffs), trusted for
//    r<=4 (symmetric window); exact serial gmem tail beyond (rare).
//  - horizontal: 6 x LDS.128 pull a 12-col float2 window; ALL r<=4 candidates
//    for all 4 pixels come from registers (exact superset-free min: every
//    candidate is a genuine j, min order-independent, monotone rounding).
//    Serial exact smem tail gated at >25 (P ~ 2^-13/px).
//  - 3-var shuffle reduction; last-block global reduction (threadfence +
//    ticket; deterministic summation order).
// ---------------------------------------------------------------------------
__global__ void __launch_bounds__(256) fused_kernel(
    const float* __restrict__ logits, const int* __restrict__ targets,
    float* __restrict__ out) {
    int blk = blockIdx.x;          // 0..511
    int b   = blk >> 6;            // image
    int h0  = (blk & 63) * 4;      // first of 4 rows
    int w   = threadIdx.x;
    int q   = w & 63;              // column quad: cols 4q..4q+3
    int i   = w >> 6;              // row within block
    int h   = h0 + i;
    int c0  = q << 2;              // first column

    // ---- prologue: all gmem loads as 128-bit ----
    const float4* L0p = (const float4*)(logits + (b * 2 + 0) * HW + h * WW) + q;
    const float4* L1p = (const float4*)(logits + (b * 2 + 1) * HW + h * WW) + q;
    float4 l0 = *L0p;
    float4 l1 = *L1p;

    int4 t[9];                     // rows h-4 .. h+4, cols 4q..4q+3
    const int4* tb = (const int4*)(targets + b * HW) + q;
    if (h >= 4 && h + 4 < HH) {
#pragma unroll
        for (int j = 0; j < 9; j++) t[j] = tb[(h - 4 + j) * (WW / 4)];
    } else {
#pragma unroll
        for (int j = 0; j < 9; j++) {
            int hh = min(max(h - 4 + j, 0), HH - 1);
            t[j] = tb[hh * (WW / 4)];
        }
    }

    __shared__ float2 srow[4][WW + 16];       // +-8 BIG pads per row
    if (w < 8) {
#pragma unroll
        for (int r = 0; r < 4; r++) {
            srow[r][w]          = make_float2(1e9f, 1e9f);
            srow[r][WW + 8 + w] = make_float2(1e9f, 1e9f);
        }
    }

    // ---- per-column 9-bit words ----
    unsigned bcol[4] = {0, 0, 0, 0};
#pragma unroll
    for (int j = 0; j < 9; j++) {
        bcol[0] |= ((unsigned)t[j].x) << j;
        bcol[1] |= ((unsigned)t[j].y) << j;
        bcol[2] |= ((unsigned)t[j].z) << j;
        bcol[3] |= ((unsigned)t[j].w) << j;
    }

    float d2p_[4], d2n_[4];
    int   me_[4];

#pragma unroll
    for (int k = 0; k < 4; k++) {
        unsigned bb = bcol[k];
        int me = (int)((bb >> 4) & 1u);
        me_[k] = me;

        // nearest 1 within r<=4: below bits 0..3 (clz; 0 -> dist 5 auto-reject),
        //                        above bits 5..8 (ffs)
        unsigned bl = bb & 0xFu;
        int dD1 = __clz(bl) - 27;              // bl=0 -> 5
        unsigned up = bb >> 5;
        int dU1 = up ? __ffs(up) : 8;
        int mn1 = min(dD1, dU1);
        int r1  = me ? 0 : ((mn1 <= 4) ? mn1 : 256);

        unsigned cb = (~bb) & 0x1FFu;
        unsigned bl0 = cb & 0xFu;
        int dD0 = __clz(bl0) - 27;
        unsigned up0 = cb >> 5;
        int dU0 = up0 ? __ffs(up0) : 8;
        int mn0 = min(dD0, dU0);
        int r0  = (me == 0) ? 0 : ((mn0 <= 4) ? mn0 : 256);

        if ((r1 | r0) >= 256) {                // rare exact serial gmem tail
            int cc = c0 + k;
            const int* tc = targets + b * HW + cc;
#pragma unroll 1
            for (int r = 5; r < HH; r++) {
                if ((r1 | r0) < 256) break;
                int tu = tc[max(h - r, 0) * WW];
                int td = tc[min(h + r, HH - 1) * WW];
                if (r1 == 256 && (tu | td))      r1 = r;
                if (r0 == 256 && (tu & td) == 0) r0 = r;
            }
        }
        d2p_[k] = (r1 <= 255) ? (float)(r1 * r1) : 1e9f;
        d2n_[k] = (r0 <= 255) ? (float)(r0 * r0) : 1e9f;
    }

    // store 4 float2 = 2 x STS.128 (16B-aligned: (8+4q)*8 = 64+32q)
    {
        float4* sp = (float4*)&srow[i][8 + c0];
        sp[0] = make_float4(d2p_[0], d2n_[0], d2p_[1], d2n_[1]);
        sp[1] = make_float4(d2p_[2], d2n_[2], d2p_[3], d2n_[3]);
    }
    __syncthreads();

    // ---- 12-col float2 window: cols 4q-4 .. 4q+7 (6 x LDS.128, aligned) ----
    float2 win[12];
    {
        const float4* wp = (const float4*)&srow[i][4 + c0];  // idx 4q+4 (even)
#pragma unroll
        for (int j = 0; j < 6; j++) {
            float4 v = wp[j];
            win[2 * j]     = make_float2(v.x, v.y);
            win[2 * j + 1] = make_float2(v.z, v.w);
        }
    }

    // sigmoid for the 4 pixels
    float px0 = __fdividef(1.0f, 1.0f + __expf(l0.x - l1.x));
    float px1 = __fdividef(1.0f, 1.0f + __expf(l0.y - l1.y));
    float px2 = __fdividef(1.0f, 1.0f + __expf(l0.z - l1.z));
    float px3 = __fdividef(1.0f, 1.0f + __expf(l0.w - l1.w));
    float pr_[4] = {px0, px1, px2, px3};

    float accP = 0.f, accW = 0.f;
    int   accC = 0;

#pragma unroll
    for (int p = 0; p < 4; p++) {
        float bp = d2p_[p], bn = d2n_[p];
        // r = 1..4 entirely from the register window (win[p-r+4], win[p+r+4])
#pragma unroll
        for (int r = 1; r <= 4; r++) {
            float rr = (float)(r * r);
            float2 a = win[p - r + 4];
            float2 d = win[p + r + 4];
            bp = fminf(bp, fminf(a.x, d.x) + rr);
            bn = fminf(bn, fminf(a.y, d.y) + rr);
        }

        if (fmaxf(bp, bn) > 25.0f) {           // rare exact serial smem tail
            int x = c0 + p;
#pragma unroll 1
            for (int r = 5; r < WW; r++) {
                float rr = (float)(r * r);
                if (rr >= bp && rr >= bn) break;
                if (x - r >= 0) {
                    float2 a = srow[i][8 + x - r];
                    bp = fminf(bp, a.x + rr); bn = fminf(bn, a.y + rr);
                }
                if (x + r < WW) {
                    float2 d = srow[i][8 + x + r];
                    bp = fminf(bp, d.x + rr); bn = fminf(bn, d.y + rr);
                }
            }
        }

        accP += pr_[p];
        accW += pr_[p] * (fsqrt_approx(bp) - fsqrt_approx(bn));
        accC += me_[p];
    }

    // ---- deterministic block reduction (3 shuffled vars, 1 barrier) ----
    unsigned m = 0xFFFFFFFFu;
    float cv = (float)accC;
#pragma unroll
    for (int o = 16; o > 0; o >>= 1) {
        accP += __shfl_down_sync(m, accP, o);
        accW += __shfl_down_sync(m, accW, o);
        cv   += __shfl_down_sync(m, cv, o);
    }
    __shared__ float rr0[8], rr1[8], rr2[8];
    if ((w & 31) == 0) {
        rr0[w >> 5] = accP; rr1[w >> 5] = accW; rr2[w >> 5] = cv;
    }
    __syncthreads();

    __shared__ bool s_last;
    if (w == 0) {
        float s0 = 0.f, s1 = 0.f, s2 = 0.f;
#pragma unroll
        for (int j = 0; j < 8; j++) { s0 += rr0[j]; s1 += rr1[j]; s2 += rr2[j]; }
        g_pp[blk] = s0;
        g_pw[blk] = s1;
        g_pc[blk] = s2;
        __threadfence();
        unsigned tk = atomicAdd(&g_ticket, 1u);
        s_last = (tk == (unsigned)(NBLK - 1));
    }
    __syncthreads();
    if (!s_last) return;

    // ---- last block: global reduction (deterministic order) ----
    int wb   = w >> 5;             // batch handled by this warp
    int lane = w & 31;
    int base = wb * 64;            // 64 partials per image
    float s0 = __ldcg(&g_pp[base + lane]) + __ldcg(&g_pp[base + 32 + lane]);
    float s1 = __ldcg(&g_pw[base + lane]) + __ldcg(&g_pw[base + 32 + lane]);
    float s2 = __ldcg(&g_pc[base + lane]) + __ldcg(&g_pc[base + 32 + lane]);
#pragma unroll
    for (int o = 16; o > 0; o >>= 1) {
        s0 += __shfl_down_sync(m, s0, o);
        s1 += __shfl_down_sync(m, s1, o);
        s2 += __shfl_down_sync(m, s2, o);
    }
    __shared__ float pb[8];
    if (lane == 0) {
        float inv = 1.0f / (float)HW;
        float mean_pred = s0 * inv;
        float mean_w    = s1 * inv;
        float per_b;
        if (s2 == 0.0f)           per_b = mean_pred;
        else if (s2 == (float)HW) per_b = 1.0f - mean_pred;
        else                      per_b = mean_w;
        pb[wb] = per_b;
    }
    __syncthreads();
    if (w == 0) {
        float total = 0.f;
#pragma unroll
        for (int j = 0; j < BB; j++) total += pb[j];
        out[0] = total / (float)BB;
        g_ticket = 0;                          // reset for next graph replay
    }
}

extern "C" void kernel_launch(void* const* d_in, const int* in_sizes, int n_in,
                              void* d_out, int out_size) {
    const float* logits  = (const float*)d_in[0];
    const int*   targets = (const int*)d_in[1];
    float*       out     = (float*)d_out;

    fused_kernel<<<NBLK, 256>>>(logits, targets, out);
}